// round 2
// baseline (speedup 1.0000x reference)
#include <cuda_runtime.h>

// Problem constants (fixed by reference)
#define BB   4
#define NN   100000
#define KK   16
#define DD   6
#define FF   13
#define LL   3
#define PTS  (BB * NN)          // 400000 points
#define SLOPE 0.2f
#define EPSN  1e-5f

// padded weight-row strides (16B alignment for LDS.128 of u64 pairs)
#define W1S  14                 // 13 cols + 1 zero pad
#define W2S  8                  // 6 cols + 2 zero pad (stride only; pads unread)
#define B1S  14

typedef unsigned long long u64;

// ---- f32x2 packed helpers (sm_103a) ----
__device__ __forceinline__ u64 pk2(float lo, float hi) {
    u64 r;
    asm("mov.b64 %0, {%1, %2};" : "=l"(r) : "f"(lo), "f"(hi));
    return r;
}
__device__ __forceinline__ void up2(u64 v, float& lo, float& hi) {
    asm("mov.b64 {%0, %1}, %2;" : "=f"(lo), "=f"(hi) : "l"(v));
}
__device__ __forceinline__ u64 ffma2(u64 a, u64 b, u64 c) {
    u64 d;
    asm("fma.rn.f32x2 %0, %1, %2, %3;" : "=l"(d) : "l"(a), "l"(b), "l"(c));
    return d;
}
__device__ __forceinline__ u64 fmul2(u64 a, u64 b) {
    u64 d;
    asm("mul.rn.f32x2 %0, %1, %2;" : "=l"(d) : "l"(a), "l"(b));
    return d;
}

__device__ __forceinline__ float leaky(float x) {
    return fmaxf(x, 0.0f) + SLOPE * fminf(x, 0.0f);
}

// packed leaky on both lanes: leaky(x) = 0.6*x + 0.4*|x|
__device__ __forceinline__ u64 leaky2(u64 x, u64 c06, u64 c04) {
    const u64 ax = x & 0x7FFFFFFF7FFFFFFFull;
    return ffma2(ax, c04, fmul2(x, c06));
}

__global__ void __launch_bounds__(256, 2)
atom_emb_mp_kernel(const float* __restrict__ dist,
                   const float* __restrict__ atomtypes,
                   const float* __restrict__ w1g,
                   const float* __restrict__ b1g,
                   const float* __restrict__ w2g,
                   const float* __restrict__ b2g,
                   const float* __restrict__ gnw,
                   const float* __restrict__ gnb,
                   float* __restrict__ out)
{
    // Packed (w,w) weights in SMEM, rows padded for LDS.128.
    __shared__ __align__(16) u64  sw1[LL * FF * W1S];   // 546 * 8 B
    __shared__ __align__(16) u64  sb1[LL * B1S];        // 42  * 8 B
    __shared__ __align__(16) u64  sw2[LL * FF * W2S];   // 312 * 8 B
    __shared__ float sb2[LL * DD];
    __shared__ float sgw[LL * DD];
    __shared__ float sgb[LL * DD];

    // zero-fill pads
    for (int i = threadIdx.x; i < LL * FF * W1S; i += blockDim.x) sw1[i] = 0ull;
    for (int i = threadIdx.x; i < LL * B1S;      i += blockDim.x) sb1[i] = 0ull;
    for (int i = threadIdx.x; i < LL * FF * W2S; i += blockDim.x) sw2[i] = 0ull;
    __syncthreads();

    for (int i = threadIdx.x; i < LL * FF * FF; i += blockDim.x) {
        const int l = i / (FF * FF), r = i % (FF * FF);
        const int ri = r / FF, rj = r % FF;
        const float w = w1g[i];
        sw1[(l * FF + ri) * W1S + rj] = pk2(w, w);
    }
    for (int i = threadIdx.x; i < LL * FF; i += blockDim.x) {
        const int l = i / FF, j = i % FF;
        const float w = b1g[i];
        sb1[l * B1S + j] = pk2(w, w);
    }
    for (int i = threadIdx.x; i < LL * FF * DD; i += blockDim.x) {
        const int l = i / (FF * DD), r = i % (FF * DD);
        const int ri = r / DD, rj = r % DD;
        const float w = w2g[i];
        sw2[(l * FF + ri) * W2S + rj] = pk2(w, w);
    }
    for (int i = threadIdx.x; i < LL * DD; i += blockDim.x) {
        sb2[i] = b2g[i];
        sgw[i] = gnw[i];
        sgb[i] = gnb[i];
    }
    __syncthreads();

    const int p = blockIdx.x * blockDim.x + threadIdx.x;
    if (p < PTS) {
        const float* atb = atomtypes + (size_t)p * (KK * DD);  // 96 floats, 16B-aligned
        const float* dsb = dist      + (size_t)p * KK;          // 16 floats

        const u64 C06 = pk2(0.6f, 0.6f);
        const u64 C04 = pk2(0.4f, 0.4f);

        float pe[DD];
        #pragma unroll
        for (int j = 0; j < DD; ++j) pe[j] = 1.0f;

        #pragma unroll 1
        for (int l = 0; l < LL; ++l) {
            const u64* w1l = sw1 + l * FF * W1S;
            const u64* b1l = sb1 + l * B1S;
            const u64* w2l = sw2 + l * FF * W2S;

            u64 pep[DD];
            #pragma unroll
            for (int j = 0; j < DD; ++j) pep[j] = pk2(pe[j], pe[j]);

            u64 acc[DD];
            #pragma unroll
            for (int j = 0; j < DD; ++j) acc[j] = 0ull;   // (0.0f, 0.0f)

            // 8 packed k-pairs: lanes (lo,hi) = neighbors (2*kp, 2*kp+1)
            #pragma unroll 1
            for (int kp = 0; kp < KK / 2; ++kp) {
                const float4* ap = (const float4*)(atb + kp * 12);
                const float4 a0 = ap[0];   // k0[0..3]
                const float4 a1 = ap[1];   // k0[4..5], k1[0..1]
                const float4 a2 = ap[2];   // k1[2..5]
                const float2 dd = *(const float2*)(dsb + kp * 2);

                u64 feat[FF];
                #pragma unroll
                for (int j = 0; j < DD; ++j) feat[j] = pep[j];
                feat[6]  = pk2(a0.x, a1.z);
                feat[7]  = pk2(a0.y, a1.w);
                feat[8]  = pk2(a0.z, a2.x);
                feat[9]  = pk2(a0.w, a2.y);
                feat[10] = pk2(a1.x, a2.z);
                feat[11] = pk2(a1.y, a2.w);
                feat[12] = pk2(dd.x, dd.y);

                // h = leaky(feat @ W1 + b1)   (169 FFMA2, 91 LDS.128-ish)
                u64 h[FF];
                {
                    const ulonglong2* bp = (const ulonglong2*)b1l;
                    #pragma unroll
                    for (int jj = 0; jj < 6; ++jj) {
                        const ulonglong2 b = bp[jj];
                        h[2 * jj]     = b.x;
                        h[2 * jj + 1] = b.y;
                    }
                    h[12] = b1l[12];
                }
                #pragma unroll
                for (int i = 0; i < FF; ++i) {
                    const u64 f = feat[i];
                    const ulonglong2* wr = (const ulonglong2*)(w1l + i * W1S);
                    #pragma unroll
                    for (int jj = 0; jj < 6; ++jj) {
                        const ulonglong2 w = wr[jj];
                        h[2 * jj]     = ffma2(f, w.x, h[2 * jj]);
                        h[2 * jj + 1] = ffma2(f, w.y, h[2 * jj + 1]);
                    }
                    h[12] = ffma2(f, w1l[i * W1S + 12], h[12]);
                }
                #pragma unroll
                for (int j = 0; j < FF; ++j) h[j] = leaky2(h[j], C06, C04);

                // acc += h @ W2               (78 FFMA2, 39 LDS.128)
                #pragma unroll
                for (int i = 0; i < FF; ++i) {
                    const u64 hh = h[i];
                    const ulonglong2* wr = (const ulonglong2*)(w2l + i * W2S);
                    #pragma unroll
                    for (int jj = 0; jj < 3; ++jj) {
                        const ulonglong2 w = wr[jj];
                        acc[2 * jj]     = ffma2(hh, w.x, acc[2 * jj]);
                        acc[2 * jj + 1] = ffma2(hh, w.y, acc[2 * jj + 1]);
                    }
                }
            }

            // reduce the two packed lanes; b2 was added once per k in the ref
            float msg[DD];
            #pragma unroll
            for (int j = 0; j < DD; ++j) {
                float x, y;
                up2(acc[j], x, y);
                msg[j] = x + y + (float)KK * sb2[l * DD + j];
            }

            // GroupNorm(2 groups of 3) + leaky + residual
            #pragma unroll
            for (int g = 0; g < 2; ++g) {
                const float m0 = msg[3 * g + 0];
                const float m1 = msg[3 * g + 1];
                const float m2 = msg[3 * g + 2];
                const float mu = (m0 + m1 + m2) * (1.0f / 3.0f);
                const float d0 = m0 - mu, d1 = m1 - mu, d2 = m2 - mu;
                const float var = (d0 * d0 + d1 * d1 + d2 * d2) * (1.0f / 3.0f);
                const float inv = rsqrtf(var + EPSN);
                const float dv[3] = {d0, d1, d2};
                #pragma unroll
                for (int c = 0; c < 3; ++c) {
                    const int ch = 3 * g + c;
                    const float v = dv[c] * inv * sgw[l * DD + ch] + sgb[l * DD + ch];
                    pe[ch] += leaky(v);
                }
            }
        }

        // point_emb out: 6 floats per point, 8B-aligned -> 3x STG.64
        float2* o = (float2*)(out + (size_t)p * DD);
        o[0] = make_float2(pe[0], pe[1]);
        o[1] = make_float2(pe[2], pe[3]);
        o[2] = make_float2(pe[4], pe[5]);
    }
}

extern "C" void kernel_launch(void* const* d_in, const int* in_sizes, int n_in,
                              void* d_out, int out_size)
{
    const float* dist      = (const float*)d_in[0];
    const float* atomtypes = (const float*)d_in[1];
    const float* w1        = (const float*)d_in[2];
    const float* b1        = (const float*)d_in[3];
    const float* w2        = (const float*)d_in[4];
    const float* b2        = (const float*)d_in[5];
    const float* gnw       = (const float*)d_in[6];
    const float* gnb       = (const float*)d_in[7];
    float* out             = (float*)d_out;

    const int threads = 256;
    const int blocks  = (PTS + threads - 1) / threads;
    atom_emb_mp_kernel<<<blocks, threads>>>(dist, atomtypes, w1, b1, w2, b2,
                                            gnw, gnb, out);
}

// round 3
// speedup vs baseline: 1.6870x; 1.6870x over previous
#include <cuda_runtime.h>

// Problem constants (fixed by reference)
#define BB   4
#define NN   100000
#define KK   16
#define DD   6
#define FF   13
#define LL   3
#define PTS  (BB * NN)          // 400000 points
#define SLOPE 0.2f
#define EPSN  1e-5f

// padded weight-row strides (16B alignment for LDS.128 of u64 pairs)
#define W1S  14                 // 13 cols + 1 zero pad
#define W2S  8                  // 6 cols + 2 zero pad (stride only; pads unread)
#define B1S  14

typedef unsigned long long u64;

// ---- f32x2 packed helpers (sm_103a) ----
__device__ __forceinline__ u64 pk2(float lo, float hi) {
    u64 r;
    asm("mov.b64 %0, {%1, %2};" : "=l"(r) : "f"(lo), "f"(hi));
    return r;
}
__device__ __forceinline__ void up2(u64 v, float& lo, float& hi) {
    asm("mov.b64 {%0, %1}, %2;" : "=f"(lo), "=f"(hi) : "l"(v));
}
__device__ __forceinline__ u64 ffma2(u64 a, u64 b, u64 c) {
    u64 d;
    asm("fma.rn.f32x2 %0, %1, %2, %3;" : "=l"(d) : "l"(a), "l"(b), "l"(c));
    return d;
}
__device__ __forceinline__ u64 fmul2(u64 a, u64 b) {
    u64 d;
    asm("mul.rn.f32x2 %0, %1, %2;" : "=l"(d) : "l"(a), "l"(b));
    return d;
}

__device__ __forceinline__ float leaky(float x) {
    return fmaxf(x, 0.0f) + SLOPE * fminf(x, 0.0f);
}

// packed leaky on both lanes: leaky(x) = 0.6*x + 0.4*|x|
__device__ __forceinline__ u64 leaky2(u64 x, u64 c06, u64 c04) {
    const u64 ax = x & 0x7FFFFFFF7FFFFFFFull;
    return ffma2(ax, c04, fmul2(x, c06));
}

__global__ void __launch_bounds__(128, 3)
atom_emb_mp_kernel(const float* __restrict__ dist,
                   const float* __restrict__ atomtypes,
                   const float* __restrict__ w1g,
                   const float* __restrict__ b1g,
                   const float* __restrict__ w2g,
                   const float* __restrict__ b2g,
                   const float* __restrict__ gnw,
                   const float* __restrict__ gnb,
                   float* __restrict__ out)
{
    // Packed (w,w) weights in SMEM, rows padded for LDS.128.
    __shared__ __align__(16) u64  sw1[LL * FF * W1S];   // 546 * 8 B
    __shared__ __align__(16) u64  sb1[LL * B1S];        // 42  * 8 B
    __shared__ __align__(16) u64  sw2[LL * FF * W2S];   // 312 * 8 B
    __shared__ float sb2[LL * DD];
    __shared__ float sgw[LL * DD];
    __shared__ float sgb[LL * DD];

    // zero-fill pads
    for (int i = threadIdx.x; i < LL * FF * W1S; i += blockDim.x) sw1[i] = 0ull;
    for (int i = threadIdx.x; i < LL * B1S;      i += blockDim.x) sb1[i] = 0ull;
    for (int i = threadIdx.x; i < LL * FF * W2S; i += blockDim.x) sw2[i] = 0ull;
    __syncthreads();

    for (int i = threadIdx.x; i < LL * FF * FF; i += blockDim.x) {
        const int l = i / (FF * FF), r = i % (FF * FF);
        const int ri = r / FF, rj = r % FF;
        const float w = w1g[i];
        sw1[(l * FF + ri) * W1S + rj] = pk2(w, w);
    }
    for (int i = threadIdx.x; i < LL * FF; i += blockDim.x) {
        const int l = i / FF, j = i % FF;
        const float w = b1g[i];
        sb1[l * B1S + j] = pk2(w, w);
    }
    for (int i = threadIdx.x; i < LL * FF * DD; i += blockDim.x) {
        const int l = i / (FF * DD), r = i % (FF * DD);
        const int ri = r / DD, rj = r % DD;
        const float w = w2g[i];
        sw2[(l * FF + ri) * W2S + rj] = pk2(w, w);
    }
    for (int i = threadIdx.x; i < LL * DD; i += blockDim.x) {
        sb2[i] = b2g[i];
        sgw[i] = gnw[i];
        sgb[i] = gnb[i];
    }
    __syncthreads();

    const int p = blockIdx.x * blockDim.x + threadIdx.x;
    if (p < PTS) {
        const float* atb = atomtypes + (size_t)p * (KK * DD);  // 96 floats, 16B-aligned
        const float* dsb = dist      + (size_t)p * KK;          // 16 floats

        const u64 C06 = pk2(0.6f, 0.6f);
        const u64 C04 = pk2(0.4f, 0.4f);

        float pe[DD];
        #pragma unroll
        for (int j = 0; j < DD; ++j) pe[j] = 1.0f;

        #pragma unroll 1
        for (int l = 0; l < LL; ++l) {
            const u64* w1l = sw1 + l * FF * W1S;
            const u64* b1l = sb1 + l * B1S;
            const u64* w2l = sw2 + l * FF * W2S;

            // --- hoisted part of feat@W1: point_emb rows (constant over k) ---
            // h_base[j] = b1[j] + sum_{i<6} pe[i] * W1[i][j]
            u64 h_base[FF];
            {
                const ulonglong2* bp = (const ulonglong2*)b1l;
                #pragma unroll
                for (int jj = 0; jj < 6; ++jj) {
                    const ulonglong2 b = bp[jj];
                    h_base[2 * jj]     = b.x;
                    h_base[2 * jj + 1] = b.y;
                }
                h_base[12] = b1l[12];
            }
            #pragma unroll
            for (int i = 0; i < DD; ++i) {
                const u64 f = pk2(pe[i], pe[i]);
                const ulonglong2* wr = (const ulonglong2*)(w1l + i * W1S);
                #pragma unroll
                for (int jj = 0; jj < 6; ++jj) {
                    const ulonglong2 w = wr[jj];
                    h_base[2 * jj]     = ffma2(f, w.x, h_base[2 * jj]);
                    h_base[2 * jj + 1] = ffma2(f, w.y, h_base[2 * jj + 1]);
                }
                h_base[12] = ffma2(f, w1l[i * W1S + 12], h_base[12]);
            }

            u64 acc[DD];
            #pragma unroll
            for (int j = 0; j < DD; ++j) acc[j] = 0ull;   // (0.0f, 0.0f)

            // 8 packed k-pairs: lanes (lo,hi) = neighbors (2*kp, 2*kp+1)
            #pragma unroll 1
            for (int kp = 0; kp < KK / 2; ++kp) {
                const float4* ap = (const float4*)(atb + kp * 12);
                const float4 a0 = ap[0];   // k0[0..3]
                const float4 a1 = ap[1];   // k0[4..5], k1[0..1]
                const float4 a2 = ap[2];   // k1[2..5]
                const float2 dd = *(const float2*)(dsb + kp * 2);

                // varying features only (atomtypes + dist)
                u64 feat[7];
                feat[0] = pk2(a0.x, a1.z);
                feat[1] = pk2(a0.y, a1.w);
                feat[2] = pk2(a0.z, a2.x);
                feat[3] = pk2(a0.w, a2.y);
                feat[4] = pk2(a1.x, a2.z);
                feat[5] = pk2(a1.y, a2.w);
                feat[6] = pk2(dd.x, dd.y);

                // h = leaky(h_base + feat_var @ W1[6..12])   (91 FFMA2)
                u64 h[FF];
                #pragma unroll
                for (int j = 0; j < FF; ++j) h[j] = h_base[j];
                #pragma unroll
                for (int i = 0; i < 7; ++i) {
                    const u64 f = feat[i];
                    const ulonglong2* wr = (const ulonglong2*)(w1l + (i + DD) * W1S);
                    #pragma unroll
                    for (int jj = 0; jj < 6; ++jj) {
                        const ulonglong2 w = wr[jj];
                        h[2 * jj]     = ffma2(f, w.x, h[2 * jj]);
                        h[2 * jj + 1] = ffma2(f, w.y, h[2 * jj + 1]);
                    }
                    h[12] = ffma2(f, w1l[(i + DD) * W1S + 12], h[12]);
                }
                #pragma unroll
                for (int j = 0; j < FF; ++j) h[j] = leaky2(h[j], C06, C04);

                // acc += h @ W2               (78 FFMA2, 39 LDS.128)
                #pragma unroll
                for (int i = 0; i < FF; ++i) {
                    const u64 hh = h[i];
                    const ulonglong2* wr = (const ulonglong2*)(w2l + i * W2S);
                    #pragma unroll
                    for (int jj = 0; jj < 3; ++jj) {
                        const ulonglong2 w = wr[jj];
                        acc[2 * jj]     = ffma2(hh, w.x, acc[2 * jj]);
                        acc[2 * jj + 1] = ffma2(hh, w.y, acc[2 * jj + 1]);
                    }
                }
            }

            // reduce the two packed lanes; b2 was added once per k in the ref
            float msg[DD];
            #pragma unroll
            for (int j = 0; j < DD; ++j) {
                float x, y;
                up2(acc[j], x, y);
                msg[j] = x + y + (float)KK * sb2[l * DD + j];
            }

            // GroupNorm(2 groups of 3) + leaky + residual
            #pragma unroll
            for (int g = 0; g < 2; ++g) {
                const float m0 = msg[3 * g + 0];
                const float m1 = msg[3 * g + 1];
                const float m2 = msg[3 * g + 2];
                const float mu = (m0 + m1 + m2) * (1.0f / 3.0f);
                const float d0 = m0 - mu, d1 = m1 - mu, d2 = m2 - mu;
                const float var = (d0 * d0 + d1 * d1 + d2 * d2) * (1.0f / 3.0f);
                const float inv = rsqrtf(var + EPSN);
                const float dv[3] = {d0, d1, d2};
                #pragma unroll
                for (int c = 0; c < 3; ++c) {
                    const int ch = 3 * g + c;
                    const float v = dv[c] * inv * sgw[l * DD + ch] + sgb[l * DD + ch];
                    pe[ch] += leaky(v);
                }
            }
        }

        // point_emb out: 6 floats per point, 8B-aligned -> 3x STG.64
        float2* o = (float2*)(out + (size_t)p * DD);
        o[0] = make_float2(pe[0], pe[1]);
        o[1] = make_float2(pe[2], pe[3]);
        o[2] = make_float2(pe[4], pe[5]);
    }
}

extern "C" void kernel_launch(void* const* d_in, const int* in_sizes, int n_in,
                              void* d_out, int out_size)
{
    const float* dist      = (const float*)d_in[0];
    const float* atomtypes = (const float*)d_in[1];
    const float* w1        = (const float*)d_in[2];
    const float* b1        = (const float*)d_in[3];
    const float* w2        = (const float*)d_in[4];
    const float* b2        = (const float*)d_in[5];
    const float* gnw       = (const float*)d_in[6];
    const float* gnb       = (const float*)d_in[7];
    float* out             = (float*)d_out;

    const int threads = 128;
    const int blocks  = (PTS + threads - 1) / threads;
    atom_emb_mp_kernel<<<blocks, threads>>>(dist, atomtypes, w1, b1, w2, b2,
                                            gnw, gnb, out);
}

// round 4
// speedup vs baseline: 2.3911x; 1.4174x over previous
#include <cuda_runtime.h>

// Problem constants (fixed by reference)
#define BB   4
#define NN   100000
#define KK   16
#define DD   6
#define FF   13
#define LL   3
#define PTS  (BB * NN)          // 400000 points
#define SLOPE 0.2f
#define EPSN  1e-5f

// padded row strides (16B alignment for LDS.128 of u64 pairs)
#define W1S  14                 // W1T row: 13 i-entries + 1 pad
#define W2S  8                  // W2 row: 6 cols + 2 pad

typedef unsigned long long u64;

// ---- f32x2 packed helpers (sm_103a) ----
__device__ __forceinline__ u64 pk2(float lo, float hi) {
    u64 r;
    asm("mov.b64 %0, {%1, %2};" : "=l"(r) : "f"(lo), "f"(hi));
    return r;
}
__device__ __forceinline__ void up2(u64 v, float& lo, float& hi) {
    asm("mov.b64 {%0, %1}, %2;" : "=f"(lo), "=f"(hi) : "l"(v));
}
__device__ __forceinline__ u64 ffma2(u64 a, u64 b, u64 c) {
    u64 d;
    asm("fma.rn.f32x2 %0, %1, %2, %3;" : "=l"(d) : "l"(a), "l"(b), "l"(c));
    return d;
}
__device__ __forceinline__ u64 fmul2(u64 a, u64 b) {
    u64 d;
    asm("mul.rn.f32x2 %0, %1, %2;" : "=l"(d) : "l"(a), "l"(b));
    return d;
}

__device__ __forceinline__ float leaky(float x) {
    return fmaxf(x, 0.0f) + SLOPE * fminf(x, 0.0f);
}

// packed leaky on both lanes: leaky(x) = 0.6*x + 0.4*|x|
__device__ __forceinline__ u64 leaky2(u64 x, u64 c06, u64 c04) {
    const u64 ax = x & 0x7FFFFFFF7FFFFFFFull;
    return ffma2(ax, c04, fmul2(x, c06));
}

__global__ void __launch_bounds__(128, 3)
atom_emb_mp_kernel(const float* __restrict__ dist,
                   const float* __restrict__ atomtypes,
                   const float* __restrict__ w1g,
                   const float* __restrict__ b1g,
                   const float* __restrict__ w2g,
                   const float* __restrict__ b2g,
                   const float* __restrict__ gnw,
                   const float* __restrict__ gnb,
                   float* __restrict__ out)
{
    // Packed (w,w) weights in SMEM. W1 stored TRANSPOSED: sw1t[l][j][i].
    __shared__ __align__(16) u64  sw1t[LL * FF * W1S];  // 546 * 8 B
    __shared__ __align__(16) u64  sb1 [LL * FF];        // 39  * 8 B
    __shared__ __align__(16) u64  sw2 [LL * FF * W2S];  // 312 * 8 B
    __shared__ float sb2[LL * DD];
    __shared__ float sgw[LL * DD];
    __shared__ float sgb[LL * DD];

    // zero-fill pads
    for (int i = threadIdx.x; i < LL * FF * W1S; i += blockDim.x) sw1t[i] = 0ull;
    for (int i = threadIdx.x; i < LL * FF * W2S; i += blockDim.x) sw2[i]  = 0ull;
    __syncthreads();

    // W1T: sw1t[(l,j),i] = W1[l][i][j]
    for (int i = threadIdx.x; i < LL * FF * FF; i += blockDim.x) {
        const int l = i / (FF * FF), r = i % (FF * FF);
        const int ri = r / FF, rj = r % FF;     // W1[l][ri][rj]
        const float w = w1g[i];
        sw1t[(l * FF + rj) * W1S + ri] = pk2(w, w);
    }
    for (int i = threadIdx.x; i < LL * FF; i += blockDim.x) {
        const float w = b1g[i];
        sb1[i] = pk2(w, w);
    }
    for (int i = threadIdx.x; i < LL * FF * DD; i += blockDim.x) {
        const int l = i / (FF * DD), r = i % (FF * DD);
        const int ri = r / DD, rj = r % DD;
        const float w = w2g[i];
        sw2[(l * FF + ri) * W2S + rj] = pk2(w, w);
    }
    for (int i = threadIdx.x; i < LL * DD; i += blockDim.x) {
        sb2[i] = b2g[i];
        sgw[i] = gnw[i];
        sgb[i] = gnb[i];
    }
    __syncthreads();

    const int p = blockIdx.x * blockDim.x + threadIdx.x;
    if (p < PTS) {
        const float* atb = atomtypes + (size_t)p * (KK * DD);  // 96 floats, 16B-aligned
        const float* dsb = dist      + (size_t)p * KK;          // 16 floats, 64B-aligned

        const u64 C06 = pk2(0.6f, 0.6f);
        const u64 C04 = pk2(0.4f, 0.4f);

        float pe[DD];
        #pragma unroll
        for (int j = 0; j < DD; ++j) pe[j] = 1.0f;

        #pragma unroll 1
        for (int l = 0; l < LL; ++l) {
            const u64* w1tl = sw1t + l * FF * W1S;
            const u64* b1l  = sb1  + l * FF;
            const u64* w2l  = sw2  + l * FF * W2S;

            u64 pep[DD];
            #pragma unroll
            for (int j = 0; j < DD; ++j) pep[j] = pk2(pe[j], pe[j]);

            // h_base[j] = b1[j] + sum_{i<6} pe[i] * W1[i][j]  (uses W1T row j, i=0..5)
            u64 h_base[FF];
            #pragma unroll
            for (int j = 0; j < FF; ++j) {
                const ulonglong2* wr = (const ulonglong2*)(w1tl + j * W1S);
                const ulonglong2 w01 = wr[0];
                const ulonglong2 w23 = wr[1];
                const ulonglong2 w45 = wr[2];
                u64 t = b1l[j];
                t = ffma2(pep[0], w01.x, t);
                t = ffma2(pep[1], w01.y, t);
                t = ffma2(pep[2], w23.x, t);
                t = ffma2(pep[3], w23.y, t);
                t = ffma2(pep[4], w45.x, t);
                t = ffma2(pep[5], w45.y, t);
                h_base[j] = t;
            }

            u64 acc[DD];
            #pragma unroll
            for (int j = 0; j < DD; ++j) acc[j] = 0ull;   // (0.0f, 0.0f)

            // 4 iterations; each handles 4 neighbors as TWO f32x2 pairs (A,B)
            // so every weight load feeds two FFMA2 streams.
            #pragma unroll 1
            for (int kq = 0; kq < KK / 4; ++kq) {
                const float4* ap = (const float4*)(atb + kq * 24);
                const float4 a0 = ap[0];   // kA0[0..3]
                const float4 a1 = ap[1];   // kA0[4..5], kA1[0..1]
                const float4 a2 = ap[2];   // kA1[2..5]
                const float4 a3 = ap[3];   // kB0[0..3]
                const float4 a4 = ap[4];   // kB0[4..5], kB1[0..1]
                const float4 a5 = ap[5];   // kB1[2..5]
                const float4 dv = *(const float4*)(dsb + kq * 4);

                u64 fA[7], fB[7];
                fA[0] = pk2(a0.x, a1.z);  fB[0] = pk2(a3.x, a4.z);
                fA[1] = pk2(a0.y, a1.w);  fB[1] = pk2(a3.y, a4.w);
                fA[2] = pk2(a0.z, a2.x);  fB[2] = pk2(a3.z, a5.x);
                fA[3] = pk2(a0.w, a2.y);  fB[3] = pk2(a3.w, a5.y);
                fA[4] = pk2(a1.x, a2.z);  fB[4] = pk2(a4.x, a5.z);
                fA[5] = pk2(a1.y, a2.w);  fB[5] = pk2(a4.y, a5.w);
                fA[6] = pk2(dv.x, dv.y);  fB[6] = pk2(dv.z, dv.w);

                #pragma unroll
                for (int j = 0; j < FF; ++j) {
                    // W1T row j, varying features i=6..12 (offset 48B: 16B-aligned)
                    const ulonglong2* wr = (const ulonglong2*)(w1tl + j * W1S + 6);
                    const ulonglong2 w67 = wr[0];
                    const ulonglong2 w89 = wr[1];
                    const ulonglong2 wab = wr[2];
                    const u64        wc  = w1tl[j * W1S + 12];

                    u64 hA = h_base[j];
                    u64 hB = h_base[j];
                    hA = ffma2(fA[0], w67.x, hA);  hB = ffma2(fB[0], w67.x, hB);
                    hA = ffma2(fA[1], w67.y, hA);  hB = ffma2(fB[1], w67.y, hB);
                    hA = ffma2(fA[2], w89.x, hA);  hB = ffma2(fB[2], w89.x, hB);
                    hA = ffma2(fA[3], w89.y, hA);  hB = ffma2(fB[3], w89.y, hB);
                    hA = ffma2(fA[4], wab.x, hA);  hB = ffma2(fB[4], wab.x, hB);
                    hA = ffma2(fA[5], wab.y, hA);  hB = ffma2(fB[5], wab.y, hB);
                    hA = ffma2(fA[6], wc,    hA);  hB = ffma2(fB[6], wc,    hB);

                    hA = leaky2(hA, C06, C04);
                    hB = leaky2(hB, C06, C04);

                    // consume immediately into acc with W2 row j
                    const ulonglong2* vr = (const ulonglong2*)(w2l + j * W2S);
                    const ulonglong2 v01 = vr[0];
                    const ulonglong2 v23 = vr[1];
                    const ulonglong2 v45 = vr[2];
                    acc[0] = ffma2(hA, v01.x, acc[0]);
                    acc[1] = ffma2(hA, v01.y, acc[1]);
                    acc[2] = ffma2(hA, v23.x, acc[2]);
                    acc[3] = ffma2(hA, v23.y, acc[3]);
                    acc[4] = ffma2(hA, v45.x, acc[4]);
                    acc[5] = ffma2(hA, v45.y, acc[5]);
                    acc[0] = ffma2(hB, v01.x, acc[0]);
                    acc[1] = ffma2(hB, v01.y, acc[1]);
                    acc[2] = ffma2(hB, v23.x, acc[2]);
                    acc[3] = ffma2(hB, v23.y, acc[3]);
                    acc[4] = ffma2(hB, v45.x, acc[4]);
                    acc[5] = ffma2(hB, v45.y, acc[5]);
                }
            }

            // reduce the two packed lanes; b2 was added once per k in the ref
            float msg[DD];
            #pragma unroll
            for (int j = 0; j < DD; ++j) {
                float x, y;
                up2(acc[j], x, y);
                msg[j] = x + y + (float)KK * sb2[l * DD + j];
            }

            // GroupNorm(2 groups of 3) + leaky + residual
            #pragma unroll
            for (int g = 0; g < 2; ++g) {
                const float m0 = msg[3 * g + 0];
                const float m1 = msg[3 * g + 1];
                const float m2 = msg[3 * g + 2];
                const float mu = (m0 + m1 + m2) * (1.0f / 3.0f);
                const float d0 = m0 - mu, d1 = m1 - mu, d2 = m2 - mu;
                const float var = (d0 * d0 + d1 * d1 + d2 * d2) * (1.0f / 3.0f);
                const float inv = rsqrtf(var + EPSN);
                const float dvv[3] = {d0, d1, d2};
                #pragma unroll
                for (int c = 0; c < 3; ++c) {
                    const int ch = 3 * g + c;
                    const float v = dvv[c] * inv * sgw[l * DD + ch] + sgb[l * DD + ch];
                    pe[ch] += leaky(v);
                }
            }
        }

        // point_emb out: 6 floats per point, 8B-aligned -> 3x STG.64
        float2* o = (float2*)(out + (size_t)p * DD);
        o[0] = make_float2(pe[0], pe[1]);
        o[1] = make_float2(pe[2], pe[3]);
        o[2] = make_float2(pe[4], pe[5]);
    }
}

extern "C" void kernel_launch(void* const* d_in, const int* in_sizes, int n_in,
                              void* d_out, int out_size)
{
    const float* dist      = (const float*)d_in[0];
    const float* atomtypes = (const float*)d_in[1];
    const float* w1        = (const float*)d_in[2];
    const float* b1        = (const float*)d_in[3];
    const float* w2        = (const float*)d_in[4];
    const float* b2        = (const float*)d_in[5];
    const float* gnw       = (const float*)d_in[6];
    const float* gnb       = (const float*)d_in[7];
    float* out             = (float*)d_out;

    const int threads = 128;
    const int blocks  = (PTS + threads - 1) / threads;
    atom_emb_mp_kernel<<<blocks, threads>>>(dist, atomtypes, w1, b1, w2, b2,
                                            gnw, gnb, out);
}

// round 5
// speedup vs baseline: 5.8129x; 2.4311x over previous
#include <cuda_runtime.h>

// Problem constants (fixed by reference)
#define BB   4
#define NN   100000
#define KK   16
#define DD   6
#define FF   13
#define LL   3
#define PTS  (BB * NN)          // 400000 points
#define SLOPE 0.2f
#define EPSN  1e-5f

#define W1S  14                 // W1T row: 13 i-entries + 1 pad (16B-aligned rows)
#define W2S  8                  // W2 row: 6 cols + 2 pad
#define TPB  128

typedef unsigned long long u64;

// ---- f32x2 packed helpers (sm_103a) ----
__device__ __forceinline__ u64 pk2(float lo, float hi) {
    u64 r;
    asm("mov.b64 %0, {%1, %2};" : "=l"(r) : "f"(lo), "f"(hi));
    return r;
}
__device__ __forceinline__ void up2(u64 v, float& lo, float& hi) {
    asm("mov.b64 {%0, %1}, %2;" : "=f"(lo), "=f"(hi) : "l"(v));
}
__device__ __forceinline__ u64 ffma2(u64 a, u64 b, u64 c) {
    u64 d;
    asm("fma.rn.f32x2 %0, %1, %2, %3;" : "=l"(d) : "l"(a), "l"(b), "l"(c));
    return d;
}
__device__ __forceinline__ u64 fmul2(u64 a, u64 b) {
    u64 d;
    asm("mul.rn.f32x2 %0, %1, %2;" : "=l"(d) : "l"(a), "l"(b));
    return d;
}

__device__ __forceinline__ float leaky(float x) {
    return fmaxf(x, 0.0f) + SLOPE * fminf(x, 0.0f);
}

// packed leaky on both lanes: leaky(x) = 0.6*x + 0.4*|x|
__device__ __forceinline__ u64 leaky2(u64 x, u64 c06, u64 c04) {
    const u64 ax = x & 0x7FFFFFFF7FFFFFFFull;
    return ffma2(ax, c04, fmul2(x, c06));
}

__global__ void __launch_bounds__(TPB, 4)
atom_emb_mp_kernel(const float* __restrict__ dist,
                   const float* __restrict__ atomtypes,
                   const float* __restrict__ w1g,
                   const float* __restrict__ b1g,
                   const float* __restrict__ w2g,
                   const float* __restrict__ b2g,
                   const float* __restrict__ gnw,
                   const float* __restrict__ gnb,
                   float* __restrict__ out)
{
    // Packed (w,w) weights in SMEM. W1 stored TRANSPOSED: sw1t[l][j][i].
    __shared__ __align__(16) u64  sw1t[LL * FF * W1S];  // 4368 B
    __shared__ __align__(16) u64  sb1 [LL * FF];        // 312 B
    __shared__ __align__(16) u64  sw2 [LL * FF * W2S];  // 2496 B
    __shared__ float sb2[LL * DD];
    __shared__ float sgw[LL * DD];
    __shared__ float sgb[LL * DD];
    // per-thread h_base scratch, [j][tid] layout: conflict-free 64-bit access
    __shared__ __align__(16) u64  hb[FF * TPB];         // 13312 B

    // zero-fill pads
    for (int i = threadIdx.x; i < LL * FF * W1S; i += blockDim.x) sw1t[i] = 0ull;
    for (int i = threadIdx.x; i < LL * FF * W2S; i += blockDim.x) sw2[i]  = 0ull;
    __syncthreads();

    // W1T: sw1t[(l,j),i] = W1[l][i][j]
    for (int i = threadIdx.x; i < LL * FF * FF; i += blockDim.x) {
        const int l = i / (FF * FF), r = i % (FF * FF);
        const int ri = r / FF, rj = r % FF;     // W1[l][ri][rj]
        const float w = w1g[i];
        sw1t[(l * FF + rj) * W1S + ri] = pk2(w, w);
    }
    for (int i = threadIdx.x; i < LL * FF; i += blockDim.x) {
        const float w = b1g[i];
        sb1[i] = pk2(w, w);
    }
    for (int i = threadIdx.x; i < LL * FF * DD; i += blockDim.x) {
        const int l = i / (FF * DD), r = i % (FF * DD);
        const int ri = r / DD, rj = r % DD;
        const float w = w2g[i];
        sw2[(l * FF + ri) * W2S + rj] = pk2(w, w);
    }
    for (int i = threadIdx.x; i < LL * DD; i += blockDim.x) {
        sb2[i] = b2g[i];
        sgw[i] = gnw[i];
        sgb[i] = gnb[i];
    }
    __syncthreads();

    const int tid = threadIdx.x;
    const int p = blockIdx.x * blockDim.x + tid;
    if (p < PTS) {
        const float* atb = atomtypes + (size_t)p * (KK * DD);  // 96 floats, 16B-aligned
        const float* dsb = dist      + (size_t)p * KK;          // 16 floats, 64B-aligned

        const u64 C06 = pk2(0.6f, 0.6f);
        const u64 C04 = pk2(0.4f, 0.4f);

        float pe[DD];
        #pragma unroll
        for (int j = 0; j < DD; ++j) pe[j] = 1.0f;

        #pragma unroll 1
        for (int l = 0; l < LL; ++l) {
            const u64* w1tl = sw1t + l * FF * W1S;
            const u64* b1l  = sb1  + l * FF;
            const u64* w2l  = sw2  + l * FF * W2S;

            u64 pep[DD];
            #pragma unroll
            for (int j = 0; j < DD; ++j) pep[j] = pk2(pe[j], pe[j]);

            // h_base[j] = b1[j] + sum_{i<6} pe[i]*W1[i][j]  -> SMEM scratch hb[j][tid]
            #pragma unroll 1
            for (int j = 0; j < FF; ++j) {
                const ulonglong2* wr = (const ulonglong2*)(w1tl + j * W1S);
                const ulonglong2 w01 = wr[0];
                const ulonglong2 w23 = wr[1];
                const ulonglong2 w45 = wr[2];
                u64 t = b1l[j];
                t = ffma2(pep[0], w01.x, t);
                t = ffma2(pep[1], w01.y, t);
                t = ffma2(pep[2], w23.x, t);
                t = ffma2(pep[3], w23.y, t);
                t = ffma2(pep[4], w45.x, t);
                t = ffma2(pep[5], w45.y, t);
                hb[j * TPB + tid] = t;
            }

            u64 acc[DD];
            #pragma unroll
            for (int j = 0; j < DD; ++j) acc[j] = 0ull;   // (0.0f, 0.0f)

            // 4 iterations; each handles 4 neighbors as TWO f32x2 pairs (A,B)
            #pragma unroll 1
            for (int kq = 0; kq < KK / 4; ++kq) {
                const float4* ap = (const float4*)(atb + kq * 24);
                const float4 a0 = ap[0];   // kA0[0..3]
                const float4 a1 = ap[1];   // kA0[4..5], kA1[0..1]
                const float4 a2 = ap[2];   // kA1[2..5]
                const float4 a3 = ap[3];   // kB0[0..3]
                const float4 a4 = ap[4];   // kB0[4..5], kB1[0..1]
                const float4 a5 = ap[5];   // kB1[2..5]
                const float4 dv = *(const float4*)(dsb + kq * 4);

                u64 fA[7], fB[7];
                fA[0] = pk2(a0.x, a1.z);  fB[0] = pk2(a3.x, a4.z);
                fA[1] = pk2(a0.y, a1.w);  fB[1] = pk2(a3.y, a4.w);
                fA[2] = pk2(a0.z, a2.x);  fB[2] = pk2(a3.z, a5.x);
                fA[3] = pk2(a0.w, a2.y);  fB[3] = pk2(a3.w, a5.y);
                fA[4] = pk2(a1.x, a2.z);  fB[4] = pk2(a4.x, a5.z);
                fA[5] = pk2(a1.y, a2.w);  fB[5] = pk2(a4.y, a5.w);
                fA[6] = pk2(dv.x, dv.y);  fB[6] = pk2(dv.z, dv.w);

                // rolled j-loop: low register pressure, small I-footprint
                const u64* w1p = w1tl;
                const u64* w2p = w2l;
                const u64* hbp = hb + tid;
                #pragma unroll 1
                for (int j = 0; j < FF; ++j) {
                    const ulonglong2* wr = (const ulonglong2*)(w1p + 6);
                    const ulonglong2 w67 = wr[0];
                    const ulonglong2 w89 = wr[1];
                    const ulonglong2 wab = wr[2];
                    const u64        wc  = w1p[12];

                    u64 hA = hbp[0];
                    u64 hB = hA;
                    hA = ffma2(fA[0], w67.x, hA);  hB = ffma2(fB[0], w67.x, hB);
                    hA = ffma2(fA[1], w67.y, hA);  hB = ffma2(fB[1], w67.y, hB);
                    hA = ffma2(fA[2], w89.x, hA);  hB = ffma2(fB[2], w89.x, hB);
                    hA = ffma2(fA[3], w89.y, hA);  hB = ffma2(fB[3], w89.y, hB);
                    hA = ffma2(fA[4], wab.x, hA);  hB = ffma2(fB[4], wab.x, hB);
                    hA = ffma2(fA[5], wab.y, hA);  hB = ffma2(fB[5], wab.y, hB);
                    hA = ffma2(fA[6], wc,    hA);  hB = ffma2(fB[6], wc,    hB);

                    hA = leaky2(hA, C06, C04);
                    hB = leaky2(hB, C06, C04);

                    const ulonglong2* vr = (const ulonglong2*)w2p;
                    const ulonglong2 v01 = vr[0];
                    const ulonglong2 v23 = vr[1];
                    const ulonglong2 v45 = vr[2];
                    acc[0] = ffma2(hA, v01.x, acc[0]);
                    acc[1] = ffma2(hA, v01.y, acc[1]);
                    acc[2] = ffma2(hA, v23.x, acc[2]);
                    acc[3] = ffma2(hA, v23.y, acc[3]);
                    acc[4] = ffma2(hA, v45.x, acc[4]);
                    acc[5] = ffma2(hA, v45.y, acc[5]);
                    acc[0] = ffma2(hB, v01.x, acc[0]);
                    acc[1] = ffma2(hB, v01.y, acc[1]);
                    acc[2] = ffma2(hB, v23.x, acc[2]);
                    acc[3] = ffma2(hB, v23.y, acc[3]);
                    acc[4] = ffma2(hB, v45.x, acc[4]);
                    acc[5] = ffma2(hB, v45.y, acc[5]);

                    w1p += W1S;
                    w2p += W2S;
                    hbp += TPB;
                }
            }

            // reduce the two packed lanes; b2 was added once per k in the ref
            float msg[DD];
            #pragma unroll
            for (int j = 0; j < DD; ++j) {
                float x, y;
                up2(acc[j], x, y);
                msg[j] = x + y + (float)KK * sb2[l * DD + j];
            }

            // GroupNorm(2 groups of 3) + leaky + residual
            #pragma unroll
            for (int g = 0; g < 2; ++g) {
                const float m0 = msg[3 * g + 0];
                const float m1 = msg[3 * g + 1];
                const float m2 = msg[3 * g + 2];
                const float mu = (m0 + m1 + m2) * (1.0f / 3.0f);
                const float d0 = m0 - mu, d1 = m1 - mu, d2 = m2 - mu;
                const float var = (d0 * d0 + d1 * d1 + d2 * d2) * (1.0f / 3.0f);
                const float inv = rsqrtf(var + EPSN);
                const float dvv[3] = {d0, d1, d2};
                #pragma unroll
                for (int c = 0; c < 3; ++c) {
                    const int ch = 3 * g + c;
                    const float v = dvv[c] * inv * sgw[l * DD + ch] + sgb[l * DD + ch];
                    pe[ch] += leaky(v);
                }
            }
        }

        // point_emb out: 6 floats per point, 8B-aligned -> 3x STG.64
        float2* o = (float2*)(out + (size_t)p * DD);
        o[0] = make_float2(pe[0], pe[1]);
        o[1] = make_float2(pe[2], pe[3]);
        o[2] = make_float2(pe[4], pe[5]);
    }
}

extern "C" void kernel_launch(void* const* d_in, const int* in_sizes, int n_in,
                              void* d_out, int out_size)
{
    const float* dist      = (const float*)d_in[0];
    const float* atomtypes = (const float*)d_in[1];
    const float* w1        = (const float*)d_in[2];
    const float* b1        = (const float*)d_in[3];
    const float* w2        = (const float*)d_in[4];
    const float* b2        = (const float*)d_in[5];
    const float* gnw       = (const float*)d_in[6];
    const float* gnb       = (const float*)d_in[7];
    float* out             = (float*)d_out;

    const int threads = TPB;
    const int blocks  = (PTS + threads - 1) / threads;
    atom_emb_mp_kernel<<<blocks, threads>>>(dist, atomtypes, w1, b1, w2, b2,
                                            gnw, gnb, out);
}

// round 6
// speedup vs baseline: 6.3615x; 1.0944x over previous
#include <cuda_runtime.h>

// Problem constants (fixed by reference)
#define BB   4
#define NN   100000
#define KK   16
#define DD   6
#define FF   13
#define LL   3
#define PTS  (BB * NN)          // 400000 points
#define SLOPE 0.2f
#define EPSN  1e-5f

#define W1S  14                 // W1T row: 13 i-entries + 1 pad (16B-aligned rows)
#define W2S  8                  // W2 row: 6 cols + 2 pad
#define TPB  128

typedef unsigned long long u64;

// ---- f32x2 packed helpers (sm_103a) ----
__device__ __forceinline__ u64 pk2(float lo, float hi) {
    u64 r;
    asm("mov.b64 %0, {%1, %2};" : "=l"(r) : "f"(lo), "f"(hi));
    return r;
}
__device__ __forceinline__ void up2(u64 v, float& lo, float& hi) {
    asm("mov.b64 {%0, %1}, %2;" : "=f"(lo), "=f"(hi) : "l"(v));
}
__device__ __forceinline__ u64 ffma2(u64 a, u64 b, u64 c) {
    u64 d;
    asm("fma.rn.f32x2 %0, %1, %2, %3;" : "=l"(d) : "l"(a), "l"(b), "l"(c));
    return d;
}
__device__ __forceinline__ u64 fmul2(u64 a, u64 b) {
    u64 d;
    asm("mul.rn.f32x2 %0, %1, %2;" : "=l"(d) : "l"(a), "l"(b));
    return d;
}

__device__ __forceinline__ float leaky(float x) {
    return fmaxf(x, 0.0f) + SLOPE * fminf(x, 0.0f);
}

// packed leaky on both lanes: leaky(x) = 0.6*x + 0.4*|x|
__device__ __forceinline__ u64 leaky2(u64 x, u64 c06, u64 c04) {
    const u64 ax = x & 0x7FFFFFFF7FFFFFFFull;
    return ffma2(ax, c04, fmul2(x, c06));
}

__global__ void __launch_bounds__(TPB, 4)
atom_emb_mp_kernel(const float* __restrict__ dist,
                   const float* __restrict__ atomtypes,
                   const float* __restrict__ w1g,
                   const float* __restrict__ b1g,
                   const float* __restrict__ w2g,
                   const float* __restrict__ b2g,
                   const float* __restrict__ gnw,
                   const float* __restrict__ gnb,
                   float* __restrict__ out)
{
    // Packed (w,w) weights in SMEM. W1 stored TRANSPOSED: sw1t[l][j][i].
    __shared__ __align__(16) u64  sw1t[LL * FF * W1S];  // 4368 B
    __shared__ __align__(16) u64  sb1 [LL * FF];        // 312 B
    __shared__ __align__(16) u64  sw2 [LL * FF * W2S];  // 2496 B
    __shared__ float sb2[LL * DD];
    __shared__ float sgw[LL * DD];
    __shared__ float sgb[LL * DD];
    // per-thread h_base scratch, [j][tid] layout: conflict-free 64-bit access
    __shared__ __align__(16) u64  hb[FF * TPB];         // 13312 B

    // zero-fill pads
    for (int i = threadIdx.x; i < LL * FF * W1S; i += blockDim.x) sw1t[i] = 0ull;
    for (int i = threadIdx.x; i < LL * FF * W2S; i += blockDim.x) sw2[i]  = 0ull;
    __syncthreads();

    // W1T: sw1t[(l,j),i] = W1[l][i][j]
    for (int i = threadIdx.x; i < LL * FF * FF; i += blockDim.x) {
        const int l = i / (FF * FF), r = i % (FF * FF);
        const int ri = r / FF, rj = r % FF;     // W1[l][ri][rj]
        const float w = w1g[i];
        sw1t[(l * FF + rj) * W1S + ri] = pk2(w, w);
    }
    for (int i = threadIdx.x; i < LL * FF; i += blockDim.x) {
        const float w = b1g[i];
        sb1[i] = pk2(w, w);
    }
    for (int i = threadIdx.x; i < LL * FF * DD; i += blockDim.x) {
        const int l = i / (FF * DD), r = i % (FF * DD);
        const int ri = r / DD, rj = r % DD;
        const float w = w2g[i];
        sw2[(l * FF + ri) * W2S + rj] = pk2(w, w);
    }
    for (int i = threadIdx.x; i < LL * DD; i += blockDim.x) {
        sb2[i] = b2g[i];
        sgw[i] = gnw[i];
        sgb[i] = gnb[i];
    }
    __syncthreads();

    const int tid = threadIdx.x;
    const int p = blockIdx.x * blockDim.x + tid;
    if (p < PTS) {
        const float* atb = atomtypes + (size_t)p * (KK * DD);  // 96 floats, 16B-aligned
        const float* dsb = dist      + (size_t)p * KK;          // 16 floats, 64B-aligned

        const u64 C06 = pk2(0.6f, 0.6f);
        const u64 C04 = pk2(0.4f, 0.4f);

        float pe[DD];
        #pragma unroll
        for (int j = 0; j < DD; ++j) pe[j] = 1.0f;

        #pragma unroll 1
        for (int l = 0; l < LL; ++l) {
            const u64* w1tl = sw1t + l * FF * W1S;
            const u64* b1l  = sb1  + l * FF;
            const u64* w2l  = sw2  + l * FF * W2S;

            u64 pep[DD];
            #pragma unroll
            for (int j = 0; j < DD; ++j) pep[j] = pk2(pe[j], pe[j]);

            // h_base[j] = b1[j] + sum_{i<6} pe[i]*W1[i][j]  -> SMEM scratch hb[j][tid]
            #pragma unroll 1
            for (int j = 0; j < FF; ++j) {
                const ulonglong2* wr = (const ulonglong2*)(w1tl + j * W1S);
                const ulonglong2 w01 = wr[0];
                const ulonglong2 w23 = wr[1];
                const ulonglong2 w45 = wr[2];
                u64 t = b1l[j];
                t = ffma2(pep[0], w01.x, t);
                t = ffma2(pep[1], w01.y, t);
                t = ffma2(pep[2], w23.x, t);
                t = ffma2(pep[3], w23.y, t);
                t = ffma2(pep[4], w45.x, t);
                t = ffma2(pep[5], w45.y, t);
                hb[j * TPB + tid] = t;
            }

            u64 acc[DD];
            #pragma unroll
            for (int j = 0; j < DD; ++j) acc[j] = 0ull;   // (0.0f, 0.0f)

            // 2 iterations; each handles 8 neighbors as FOUR f32x2 streams
            // so every weight load feeds four FFMA2 streams.
            #pragma unroll 1
            for (int kq = 0; kq < KK / 8; ++kq) {
                const float4* ap = (const float4*)(atb + kq * 48);
                const float4 a0  = ap[0];
                const float4 a1  = ap[1];
                const float4 a2  = ap[2];
                const float4 a3  = ap[3];
                const float4 a4  = ap[4];
                const float4 a5  = ap[5];
                const float4 a6  = ap[6];
                const float4 a7  = ap[7];
                const float4 a8  = ap[8];
                const float4 a9  = ap[9];
                const float4 a10 = ap[10];
                const float4 a11 = ap[11];
                const float4 dv0 = *(const float4*)(dsb + kq * 8);
                const float4 dv1 = *(const float4*)(dsb + kq * 8 + 4);

                u64 fA[7], fB[7], fC[7], fD[7];
                fA[0] = pk2(a0.x, a1.z);  fB[0] = pk2(a3.x, a4.z);
                fA[1] = pk2(a0.y, a1.w);  fB[1] = pk2(a3.y, a4.w);
                fA[2] = pk2(a0.z, a2.x);  fB[2] = pk2(a3.z, a5.x);
                fA[3] = pk2(a0.w, a2.y);  fB[3] = pk2(a3.w, a5.y);
                fA[4] = pk2(a1.x, a2.z);  fB[4] = pk2(a4.x, a5.z);
                fA[5] = pk2(a1.y, a2.w);  fB[5] = pk2(a4.y, a5.w);
                fA[6] = pk2(dv0.x, dv0.y); fB[6] = pk2(dv0.z, dv0.w);
                fC[0] = pk2(a6.x, a7.z);  fD[0] = pk2(a9.x, a10.z);
                fC[1] = pk2(a6.y, a7.w);  fD[1] = pk2(a9.y, a10.w);
                fC[2] = pk2(a6.z, a8.x);  fD[2] = pk2(a9.z, a11.x);
                fC[3] = pk2(a6.w, a8.y);  fD[3] = pk2(a9.w, a11.y);
                fC[4] = pk2(a7.x, a8.z);  fD[4] = pk2(a10.x, a11.z);
                fC[5] = pk2(a7.y, a8.w);  fD[5] = pk2(a10.y, a11.w);
                fC[6] = pk2(dv1.x, dv1.y); fD[6] = pk2(dv1.z, dv1.w);

                // rolled j-loop: low register pressure, small I-footprint
                const u64* w1p = w1tl;
                const u64* w2p = w2l;
                const u64* hbp = hb + tid;
                #pragma unroll 1
                for (int j = 0; j < FF; ++j) {
                    const ulonglong2* wr = (const ulonglong2*)(w1p + 6);
                    const ulonglong2 w67 = wr[0];
                    const ulonglong2 w89 = wr[1];
                    const ulonglong2 wab = wr[2];
                    const u64        wc  = w1p[12];

                    u64 hA = hbp[0];
                    u64 hB = hA, hC = hA, hD = hA;
                    hA = ffma2(fA[0], w67.x, hA);  hB = ffma2(fB[0], w67.x, hB);
                    hC = ffma2(fC[0], w67.x, hC);  hD = ffma2(fD[0], w67.x, hD);
                    hA = ffma2(fA[1], w67.y, hA);  hB = ffma2(fB[1], w67.y, hB);
                    hC = ffma2(fC[1], w67.y, hC);  hD = ffma2(fD[1], w67.y, hD);
                    hA = ffma2(fA[2], w89.x, hA);  hB = ffma2(fB[2], w89.x, hB);
                    hC = ffma2(fC[2], w89.x, hC);  hD = ffma2(fD[2], w89.x, hD);
                    hA = ffma2(fA[3], w89.y, hA);  hB = ffma2(fB[3], w89.y, hB);
                    hC = ffma2(fC[3], w89.y, hC);  hD = ffma2(fD[3], w89.y, hD);
                    hA = ffma2(fA[4], wab.x, hA);  hB = ffma2(fB[4], wab.x, hB);
                    hC = ffma2(fC[4], wab.x, hC);  hD = ffma2(fD[4], wab.x, hD);
                    hA = ffma2(fA[5], wab.y, hA);  hB = ffma2(fB[5], wab.y, hB);
                    hC = ffma2(fC[5], wab.y, hC);  hD = ffma2(fD[5], wab.y, hD);
                    hA = ffma2(fA[6], wc,    hA);  hB = ffma2(fB[6], wc,    hB);
                    hC = ffma2(fC[6], wc,    hC);  hD = ffma2(fD[6], wc,    hD);

                    hA = leaky2(hA, C06, C04);
                    hB = leaky2(hB, C06, C04);
                    hC = leaky2(hC, C06, C04);
                    hD = leaky2(hD, C06, C04);

                    const ulonglong2* vr = (const ulonglong2*)w2p;
                    const ulonglong2 v01 = vr[0];
                    const ulonglong2 v23 = vr[1];
                    const ulonglong2 v45 = vr[2];
                    acc[0] = ffma2(hA, v01.x, acc[0]);
                    acc[1] = ffma2(hA, v01.y, acc[1]);
                    acc[2] = ffma2(hA, v23.x, acc[2]);
                    acc[3] = ffma2(hA, v23.y, acc[3]);
                    acc[4] = ffma2(hA, v45.x, acc[4]);
                    acc[5] = ffma2(hA, v45.y, acc[5]);
                    acc[0] = ffma2(hB, v01.x, acc[0]);
                    acc[1] = ffma2(hB, v01.y, acc[1]);
                    acc[2] = ffma2(hB, v23.x, acc[2]);
                    acc[3] = ffma2(hB, v23.y, acc[3]);
                    acc[4] = ffma2(hB, v45.x, acc[4]);
                    acc[5] = ffma2(hB, v45.y, acc[5]);
                    acc[0] = ffma2(hC, v01.x, acc[0]);
                    acc[1] = ffma2(hC, v01.y, acc[1]);
                    acc[2] = ffma2(hC, v23.x, acc[2]);
                    acc[3] = ffma2(hC, v23.y, acc[3]);
                    acc[4] = ffma2(hC, v45.x, acc[4]);
                    acc[5] = ffma2(hC, v45.y, acc[5]);
                    acc[0] = ffma2(hD, v01.x, acc[0]);
                    acc[1] = ffma2(hD, v01.y, acc[1]);
                    acc[2] = ffma2(hD, v23.x, acc[2]);
                    acc[3] = ffma2(hD, v23.y, acc[3]);
                    acc[4] = ffma2(hD, v45.x, acc[4]);
                    acc[5] = ffma2(hD, v45.y, acc[5]);

                    w1p += W1S;
                    w2p += W2S;
                    hbp += TPB;
                }
            }

            // reduce the two packed lanes; b2 was added once per k in the ref
            float msg[DD];
            #pragma unroll
            for (int j = 0; j < DD; ++j) {
                float x, y;
                up2(acc[j], x, y);
                msg[j] = x + y + (float)KK * sb2[l * DD + j];
            }

            // GroupNorm(2 groups of 3) + leaky + residual
            #pragma unroll
            for (int g = 0; g < 2; ++g) {
                const float m0 = msg[3 * g + 0];
                const float m1 = msg[3 * g + 1];
                const float m2 = msg[3 * g + 2];
                const float mu = (m0 + m1 + m2) * (1.0f / 3.0f);
                const float d0 = m0 - mu, d1 = m1 - mu, d2 = m2 - mu;
                const float var = (d0 * d0 + d1 * d1 + d2 * d2) * (1.0f / 3.0f);
                const float inv = rsqrtf(var + EPSN);
                const float dvv[3] = {d0, d1, d2};
                #pragma unroll
                for (int c = 0; c < 3; ++c) {
                    const int ch = 3 * g + c;
                    const float v = dvv[c] * inv * sgw[l * DD + ch] + sgb[l * DD + ch];
                    pe[ch] += leaky(v);
                }
            }
        }

        // point_emb out: 6 floats per point, 8B-aligned -> 3x STG.64
        float2* o = (float2*)(out + (size_t)p * DD);
        o[0] = make_float2(pe[0], pe[1]);
        o[1] = make_float2(pe[2], pe[3]);
        o[2] = make_float2(pe[4], pe[5]);
    }
}

extern "C" void kernel_launch(void* const* d_in, const int* in_sizes, int n_in,
                              void* d_out, int out_size)
{
    const float* dist      = (const float*)d_in[0];
    const float* atomtypes = (const float*)d_in[1];
    const float* w1        = (const float*)d_in[2];
    const float* b1        = (const float*)d_in[3];
    const float* w2        = (const float*)d_in[4];
    const float* b2        = (const float*)d_in[5];
    const float* gnw       = (const float*)d_in[6];
    const float* gnb       = (const float*)d_in[7];
    float* out             = (float*)d_out;

    const int threads = TPB;
    const int blocks  = (PTS + threads - 1) / threads;
    atom_emb_mp_kernel<<<blocks, threads>>>(dist, atomtypes, w1, b1, w2, b2,
                                            gnw, gnb, out);
}